// round 3
// baseline (speedup 1.0000x reference)
#include <cuda_runtime.h>

// Problem constants (from reference: B=2048, N=60, C=128)
#define BCOL 2048
#define NL   60
#define CCH  128
#define BLOCK 128
#define E    2                      // independent (b,c) elements per thread
#define HALF (BCOL * CCH / E)       // 131072 threads

// dynamic smem: rs[]/rt[] for E elements, [layer][elem][thread]
#define SMEM_FLOATS (NL * E * BLOCK)
#define SMEM_BYTES  (SMEM_FLOATS * sizeof(float))

__device__ __forceinline__ float frcp(float x) {
    return __fdividef(1.0f, x);     // MUFU.RCP path, ~2ulp
}

__global__ __launch_bounds__(BLOCK, 3)
void adding_doubling_kernel(const float* __restrict__ a,
                            const float* __restrict__ r,
                            const float* __restrict__ t,
                            const float* __restrict__ s,
                            float* __restrict__ out)
{
    extern __shared__ float smem[];
    const int tx = threadIdx.x;
    const int tid = blockIdx.x * BLOCK + tx;
    if (tid >= HALF) return;

    size_t base[E];
#pragma unroll
    for (int e = 0; e < E; ++e) {
        int id = tid + e * HALF;
        int b = id >> 7;               // id / CCH
        int c = id & (CCH - 1);        // id % CCH
        base[e] = (size_t)b * (NL * CCH) + c;
    }

    const size_t BNC = (size_t)BCOL * NL * CCH;
    float* fd = out;            // flux_down
    float* fu = out + BNC;      // flux_up
    float* ab = out + 2 * BNC;  // absorbed

#define SH_R(e, l) smem[((l) * E + (e)) * BLOCK + tx]

    // ---------------- Phase A: bottom-up cumulative surface reflection ----
    // rs[N-1]=r[N-1]; l=N-2..1: ds=1/(1-rs*r); rs = r + rs*t^2*ds
    {
        float rs_run[E];
#pragma unroll
        for (int e = 0; e < E; ++e) {
            rs_run[e] = r[base[e] + (size_t)(NL - 1) * CCH];
            SH_R(e, NL - 1) = rs_run[e];
        }
#pragma unroll 2
        for (int l = NL - 2; l >= 1; --l) {    // rs[0] never consumed
#pragma unroll
            for (int e = 0; e < E; ++e) {
                size_t idx = base[e] + (size_t)l * CCH;
                float rl = r[idx];
                float tl = t[idx];
                float dd = frcp(1.0f - rs_run[e] * rl);
                rs_run[e] = rl + rs_run[e] * tl * tl * dd;
                SH_R(e, l) = rs_run[e];
            }
        }
    }

    // ---------------- Phase B: forward — down flux + top-down rt ----------
    {
        float s_prev[E], r_prev[E], ds_prev[E], rt_run[E], F[E];
#pragma unroll
        for (int e = 0; e < E; ++e) {
            s_prev[e] = s[base[e]];
            r_prev[e] = r[base[e]];
            float rs1 = SH_R(e, 1);
            ds_prev[e] = frcp(1.0f - rs1 * r_prev[e]);   // ds[0]
            rt_run[e] = r_prev[e];                        // rt[0] = r[0]
            SH_R(e, 0) = rt_run[e];
            __stcs(&fd[base[e]], 0.0f);     // flux_down[0] (never re-read)
            ab[base[e]] = 0.0f;             // placeholder (final set in C)
            F[e] = 0.0f;
        }

#pragma unroll 2
        for (int l = 1; l < NL; ++l) {
#pragma unroll
            for (int e = 0; e < E; ++e) {
                size_t idx = base[e] + (size_t)l * CCH;
                float sl = s[idx];
                float rl = r[idx];
                float tl = t[idx];
                float al = a[idx];

                float s_down = ds_prev[e] * (s_prev[e] + sl * r_prev[e]);
                float G = F[e] + s_down;
                __stcs(&fd[idx], G);        // streaming: never re-read

                float absd;
                if (l < NL - 1) {
                    float rsl1 = SH_R(e, l + 1);             // rs[l+1]
                    float dsl  = frcp(1.0f - rsl1 * rl);     // ds[l]
                    float td = tl * dsl;
                    absd = al * (1.0f + rsl1 * td) * G;
                    F[e] = G * td;
                    ds_prev[e] = dsl;
                } else {
                    absd = al * G;
                }
                ab[idx] = absd;             // default: re-read in phase C

                // rt update; overwrite dead rs[l] slot with rt[l]
                float dd = frcp(1.0f - rt_run[e] * rl);
                rt_run[e] = rl + rt_run[e] * tl * tl * dd;
                SH_R(e, l) = rt_run[e];

                s_prev[e] = sl;
                r_prev[e] = rl;
            }
        }
    }

    // ---------------- Phase C: reverse — up flux ---------------------------
    {
        float Fu[E], s_m[E], r_m[E], dt_m[E];
#pragma unroll
        for (int e = 0; e < E; ++e) {
            Fu[e] = 0.0f;
            size_t idxN = base[e] + (size_t)(NL - 1) * CCH;
            s_m[e] = __ldcs(&s[idxN]);     // last use of these inputs
            r_m[e] = __ldcs(&r[idxN]);
            float rt_m1 = SH_R(e, NL - 2);
            dt_m[e] = frcp(1.0f - rt_m1 * r_m[e]);   // dt[N-1]
        }

#pragma unroll 2
        for (int m = NL - 1; m >= 2; --m) {
#pragma unroll
            for (int e = 0; e < E; ++e) {
                size_t idxm1 = base[e] + (size_t)(m - 1) * CCH;
                float s_m1 = __ldcs(&s[idxm1]);
                float r_m1 = __ldcs(&r[idxm1]);
                float t_m1 = __ldcs(&t[idxm1]);
                float a_m1 = __ldcs(&a[idxm1]);
                float ab_old = ab[idxm1];              // absorbed_down[m-1]

                float rt_m2 = SH_R(e, m - 2);
                float dt_m1 = frcp(1.0f - rt_m2 * r_m1);   // dt[m-1]

                float s_up_m = dt_m[e] * (s_m[e] + s_m1 * r_m[e]);
                float G = Fu[e] + s_up_m;
                __stcs(&fu[base[e] + (size_t)m * CCH], G);

                float tdm1 = t_m1 * dt_m1;
                float au = G * a_m1 * (1.0f + rt_m2 * tdm1);
                __stcs(&ab[idxm1], ab_old + au);       // final value
                Fu[e] = G * tdm1;

                s_m[e] = s_m1;
                r_m[e] = r_m1;
                dt_m[e] = dt_m1;
            }
        }

        // m = 1 and m = 0 tail; loop left s_m=s[1], r_m=r[1], dt_m=dt[1]
#pragma unroll
        for (int e = 0; e < E; ++e) {
            float s0 = __ldcs(&s[base[e]]);
            float t0 = __ldcs(&t[base[e]]);
            float a0 = __ldcs(&a[base[e]]);
            float s_up1 = dt_m[e] * (s_m[e] + s0 * r_m[e]);
            float flux1 = Fu[e] + s_up1;
            __stcs(&fu[base[e] + CCH], flux1);           // flux_up[1]
            __stcs(&ab[base[e]], flux1 * a0);            // absorbed[0]
            __stcs(&fu[base[e]], flux1 * t0 + s0);       // flux_up[0]
        }
    }

#undef SH_R
}

extern "C" void kernel_launch(void* const* d_in, const int* in_sizes, int n_in,
                              void* d_out, int out_size)
{
    const float* a = (const float*)d_in[0];
    const float* r = (const float*)d_in[1];
    const float* t = (const float*)d_in[2];
    const float* s = (const float*)d_in[3];
    float* out = (float*)d_out;

    cudaFuncSetAttribute(adding_doubling_kernel,
                         cudaFuncAttributeMaxDynamicSharedMemorySize,
                         (int)SMEM_BYTES);

    const int grid = (HALF + BLOCK - 1) / BLOCK;   // 1024 blocks
    adding_doubling_kernel<<<grid, BLOCK, SMEM_BYTES>>>(a, r, t, s, out);
}

// round 4
// speedup vs baseline: 2.1954x; 2.1954x over previous
#include <cuda_runtime.h>

// Problem constants (from reference: B=2048, N=60, C=128)
#define BCOL 2048
#define NL   60
#define CCH  128
#define BLOCK 128

// dynamic smem: ONE per-thread array of NL floats, [layer][thread].
// Holds rs[] (phase A), progressively overwritten by rt[] (phase B).
#define SMEM_FLOATS (NL * BLOCK)
#define SMEM_BYTES  (SMEM_FLOATS * sizeof(float))

__device__ __forceinline__ float frcp(float x) {
    return __fdividef(1.0f, x);     // MUFU.RCP path, ~2ulp
}

__global__ __launch_bounds__(BLOCK, 7)   // cap regs at 73 to keep 7 blocks/SM
void adding_doubling_kernel(const float* __restrict__ a,
                            const float* __restrict__ r,
                            const float* __restrict__ t,
                            const float* __restrict__ s,
                            float* __restrict__ out)
{
    extern __shared__ float smem[];
    float* sh_r = smem;
    const int tx = threadIdx.x;

    int tid = blockIdx.x * BLOCK + tx;
    if (tid >= BCOL * CCH) return;

    const int b = tid >> 7;          // tid / CCH
    const int c = tid & (CCH - 1);   // tid % CCH
    const size_t base = (size_t)b * (NL * CCH) + c;
    const size_t BNC  = (size_t)BCOL * NL * CCH;

    float* fd = out;            // flux_down
    float* fu = out + BNC;      // flux_up
    float* ab = out + 2 * BNC;  // absorbed

#define SH_R(l) sh_r[(l) * BLOCK + tx]

    // ---------------- Phase A: bottom-up cumulative surface reflection ----
    // rs[N-1]=r[N-1]; l=N-2..1: ds=1/(1-rs*r); rs = r + rs*t^2*ds
    {
        float rs_run = r[base + (size_t)(NL - 1) * CCH];
        SH_R(NL - 1) = rs_run;

        // 1-ahead prefetch pipeline
        float rl = r[base + (size_t)(NL - 2) * CCH];
        float tl = t[base + (size_t)(NL - 2) * CCH];
        #pragma unroll 2
        for (int l = NL - 2; l >= 1; --l) {
            float rn, tn;
            if (l > 1) {
                size_t nidx = base + (size_t)(l - 1) * CCH;
                rn = r[nidx];
                tn = t[nidx];
            }
            float dd = frcp(1.0f - rs_run * rl);
            rs_run = rl + rs_run * tl * tl * dd;
            SH_R(l) = rs_run;
            rl = rn;
            tl = tn;
        }
    }

    // ---------------- Phase B: forward — down flux + top-down rt ----------
    {
        float s_prev = s[base];
        float r_prev = r[base];
        float rs1 = SH_R(1);
        float ds_prev = frcp(1.0f - rs1 * r_prev);   // ds[0]
        float rt_run = r_prev;                        // rt[0] = r[0]
        SH_R(0) = rt_run;
        __stcs(&fd[base], 0.0f);     // flux_down[0] (never re-read)
        ab[base] = 0.0f;             // placeholder (final value set in C)

        float F = 0.0f;
        // prefetch layer 1
        float sl = s[base + CCH];
        float rl = r[base + CCH];
        float tl = t[base + CCH];
        float al = a[base + CCH];

        #pragma unroll 2
        for (int l = 1; l < NL; ++l) {
            float sn, rn, tn, an;
            if (l + 1 < NL) {
                size_t nidx = base + (size_t)(l + 1) * CCH;
                sn = s[nidx];
                rn = r[nidx];
                tn = t[nidx];
                an = a[nidx];
            }
            size_t idx = base + (size_t)l * CCH;

            float s_down = ds_prev * (s_prev + sl * r_prev);
            float G = F + s_down;
            __stcs(&fd[idx], G);         // streaming write

            float absd;
            if (l < NL - 1) {
                float rsl1 = SH_R(l + 1);               // rs[l+1]
                float dsl  = frcp(1.0f - rsl1 * rl);    // ds[l]
                float td = tl * dsl;
                absd = al * (1.0f + rsl1 * td) * G;
                F = G * td;
                ds_prev = dsl;
            } else {
                absd = al * G;
            }
            ab[idx] = absd;              // re-read in phase C → default store

            // rt update; overwrite dead rs[l] slot with rt[l]
            float dd = frcp(1.0f - rt_run * rl);
            rt_run = rl + rt_run * tl * tl * dd;
            SH_R(l) = rt_run;

            s_prev = sl;
            r_prev = rl;
            sl = sn; rl = rn; tl = tn; al = an;
        }
    }

    // ---------------- Phase C: reverse — up flux ---------------------------
    {
        float Fu = 0.0f;
        size_t idxN = base + (size_t)(NL - 1) * CCH;
        float s_m = __ldcs(&s[idxN]);
        float r_m = __ldcs(&r[idxN]);
        float rt_m1 = SH_R(NL - 2);
        float dt_m = frcp(1.0f - rt_m1 * r_m);   // dt[N-1]

        // prefetch layer (m-1) = NL-2 data for first iteration
        size_t pidx = base + (size_t)(NL - 2) * CCH;
        float s_c = __ldcs(&s[pidx]);
        float r_c = __ldcs(&r[pidx]);
        float t_c = __ldcs(&t[pidx]);
        float a_c = __ldcs(&a[pidx]);
        float ab_c = ab[pidx];

        #pragma unroll 2
        for (int m = NL - 1; m >= 2; --m) {
            // issue next iteration's loads (layer m-2) early
            float s_n, r_n, t_n, a_n, ab_n;
            if (m > 2) {
                size_t nidx = base + (size_t)(m - 2) * CCH;
                s_n = __ldcs(&s[nidx]);
                r_n = __ldcs(&r[nidx]);
                t_n = __ldcs(&t[nidx]);
                a_n = __ldcs(&a[nidx]);
                ab_n = ab[nidx];
            }

            float rt_m2 = SH_R(m - 2);
            float dt_m1 = frcp(1.0f - rt_m2 * r_c);   // dt[m-1]

            float s_up_m = dt_m * (s_m + s_c * r_m);
            float G = Fu + s_up_m;
            __stcs(&fu[base + (size_t)m * CCH], G);

            float tdm1 = t_c * dt_m1;
            float au = G * a_c * (1.0f + rt_m2 * tdm1);
            __stcs(&ab[base + (size_t)(m - 1) * CCH], ab_c + au);  // final
            Fu = G * tdm1;

            s_m = s_c;
            r_m = r_c;
            dt_m = dt_m1;
            s_c = s_n; r_c = r_n; t_c = t_n; a_c = a_n; ab_c = ab_n;
        }

        // m = 1 and m = 0 tail; loop left s_m=s[1], r_m=r[1], dt_m=dt[1]
        float s0 = __ldcs(&s[base]);
        float t0 = __ldcs(&t[base]);
        float a0 = __ldcs(&a[base]);
        float s_up1 = dt_m * (s_m + s0 * r_m);
        float flux1 = Fu + s_up1;
        __stcs(&fu[base + CCH], flux1);           // flux_up[1]
        __stcs(&ab[base], flux1 * a0);            // absorbed[0] (down = 0)
        __stcs(&fu[base], flux1 * t0 + s0);       // flux_up[0]
    }

#undef SH_R
}

extern "C" void kernel_launch(void* const* d_in, const int* in_sizes, int n_in,
                              void* d_out, int out_size)
{
    const float* a = (const float*)d_in[0];
    const float* r = (const float*)d_in[1];
    const float* t = (const float*)d_in[2];
    const float* s = (const float*)d_in[3];
    float* out = (float*)d_out;

    cudaFuncSetAttribute(adding_doubling_kernel,
                         cudaFuncAttributeMaxDynamicSharedMemorySize,
                         (int)SMEM_BYTES);

    const int total = BCOL * CCH;                 // 262144 threads
    const int grid = (total + BLOCK - 1) / BLOCK; // 2048 blocks
    adding_doubling_kernel<<<grid, BLOCK, SMEM_BYTES>>>(a, r, t, s, out);
}

// round 5
// speedup vs baseline: 2.6566x; 1.2101x over previous
#include <cuda_runtime.h>

// Problem constants (from reference: B=2048, N=60, C=128)
#define BCOL 2048
#define NL   60
#define CCH  128
#define BLOCK 128

// dynamic smem: ONE per-thread array of NL floats, [layer][thread].
// Holds rs[] (phase A), progressively overwritten by rt[] (phase B).
#define SMEM_FLOATS (NL * BLOCK)
#define SMEM_BYTES  (SMEM_FLOATS * sizeof(float))

__device__ __forceinline__ float frcp(float x) {
    return __fdividef(1.0f, x);     // MUFU.RCP path, ~2ulp
}

__global__ __launch_bounds__(BLOCK, 7)   // keep 7 blocks/SM (28 warps)
void adding_doubling_kernel(const float* __restrict__ a,
                            const float* __restrict__ r,
                            const float* __restrict__ t,
                            const float* __restrict__ s,
                            float* __restrict__ out)
{
    extern __shared__ float smem[];
    float* sh_r = smem;
    const int tx = threadIdx.x;

    const unsigned tid = blockIdx.x * BLOCK + tx;
    const unsigned b = tid >> 7;          // tid / CCH
    const unsigned c = tid & (CCH - 1);   // tid % CCH
    const unsigned base = b * (NL * CCH) + c;   // < 2^24, fits 32-bit
    const unsigned BNC  = BCOL * NL * CCH;

    float* fd = out;            // flux_down
    float* fu = out + BNC;      // flux_up
    float* ab = out + 2u * BNC; // absorbed

#define SH_R(l) sh_r[(l) * BLOCK + tx]

    // ---------------- Phase A: bottom-up cumulative surface reflection ----
    // rs[N-1]=r[N-1]; l=N-2..1: ds=1/(1-rs*r); rs = r + rs*t^2*ds
    {
        float rs_run = r[base + (NL - 1) * CCH];
        SH_R(NL - 1) = rs_run;

        int l = NL - 2;
        for (; l - 3 >= 1; l -= 4) {
            float rv[4], tv[4];
            #pragma unroll
            for (int k = 0; k < 4; ++k) {       // 8 loads back-to-back
                unsigned idx = base + (unsigned)(l - k) * CCH;
                rv[k] = r[idx];
                tv[k] = t[idx];
            }
            #pragma unroll
            for (int k = 0; k < 4; ++k) {
                float dd = frcp(1.0f - rs_run * rv[k]);
                rs_run = rv[k] + rs_run * tv[k] * tv[k] * dd;
                SH_R(l - k) = rs_run;
            }
        }
        for (; l >= 1; --l) {                   // tail (l = 2, 1)
            unsigned idx = base + (unsigned)l * CCH;
            float rl = r[idx], tl = t[idx];
            float dd = frcp(1.0f - rs_run * rl);
            rs_run = rl + rs_run * tl * tl * dd;
            SH_R(l) = rs_run;
        }
    }

    // ---------------- Phase B: forward — down flux + top-down rt ----------
    {
        float s_prev = s[base];
        float r_prev = r[base];
        float rs1 = SH_R(1);
        float ds_prev = frcp(1.0f - rs1 * r_prev);   // ds[0]
        float rt_run = r_prev;                        // rt[0] = r[0]
        SH_R(0) = rt_run;
        __stcs(&fd[base], 0.0f);     // flux_down[0] (never re-read)
        float F = 0.0f;

        int l = 1;
        for (; l + 3 <= NL - 2; l += 4) {       // all-normal batches
            float sv[4], rv[4], tv[4], av[4], rsv[4];
            #pragma unroll
            for (int k = 0; k < 4; ++k) {       // 16 loads back-to-back
                unsigned idx = base + (unsigned)(l + k) * CCH;
                sv[k] = s[idx];
                rv[k] = r[idx];
                tv[k] = t[idx];
                av[k] = a[idx];
            }
            #pragma unroll
            for (int k = 0; k < 4; ++k)
                rsv[k] = SH_R(l + k + 1);       // rs[l+k+1]
            #pragma unroll
            for (int k = 0; k < 4; ++k) {
                unsigned idx = base + (unsigned)(l + k) * CCH;
                float s_down = ds_prev * (s_prev + sv[k] * r_prev);
                float G = F + s_down;
                __stcs(&fd[idx], G);

                float dsl = frcp(1.0f - rsv[k] * rv[k]);   // ds[l+k]
                float td = tv[k] * dsl;
                ab[idx] = av[k] * (1.0f + rsv[k] * td) * G; // re-read in C
                F = G * td;
                ds_prev = dsl;

                float dd = frcp(1.0f - rt_run * rv[k]);
                rt_run = rv[k] + rt_run * tv[k] * tv[k] * dd;
                SH_R(l + k) = rt_run;           // overwrite dead rs slot

                s_prev = sv[k];
                r_prev = rv[k];
            }
        }
        for (; l < NL; ++l) {                   // tail l = 57, 58, 59
            unsigned idx = base + (unsigned)l * CCH;
            float sl = s[idx], rl = r[idx], tl = t[idx], al = a[idx];

            float s_down = ds_prev * (s_prev + sl * r_prev);
            float G = F + s_down;
            __stcs(&fd[idx], G);

            float absd;
            if (l < NL - 1) {
                float rsl1 = SH_R(l + 1);
                float dsl  = frcp(1.0f - rsl1 * rl);
                float td = tl * dsl;
                absd = al * (1.0f + rsl1 * td) * G;
                F = G * td;
                ds_prev = dsl;
            } else {
                absd = al * G;
            }
            ab[idx] = absd;

            float dd = frcp(1.0f - rt_run * rl);
            rt_run = rl + rt_run * tl * tl * dd;
            SH_R(l) = rt_run;

            s_prev = sl;
            r_prev = rl;
        }
    }

    // ---------------- Phase C: reverse — up flux ---------------------------
    {
        float Fu = 0.0f;
        unsigned idxN = base + (NL - 1) * CCH;
        float s_m = __ldcs(&s[idxN]);
        float r_m = __ldcs(&r[idxN]);
        float dt_m = frcp(1.0f - SH_R(NL - 2) * r_m);   // dt[N-1]

        int m = NL - 1;
        for (; m - 3 >= 2; m -= 4) {
            float sv[4], rv[4], tv[4], av[4], abv[4], rtv[4];
            #pragma unroll
            for (int k = 0; k < 4; ++k) {       // 20 loads back-to-back
                unsigned idx = base + (unsigned)(m - 1 - k) * CCH;
                sv[k]  = __ldcs(&s[idx]);       // last use of inputs
                rv[k]  = __ldcs(&r[idx]);
                tv[k]  = __ldcs(&t[idx]);
                av[k]  = __ldcs(&a[idx]);
                abv[k] = ab[idx];               // absorbed_down[m-1-k]
            }
            #pragma unroll
            for (int k = 0; k < 4; ++k)
                rtv[k] = SH_R(m - 2 - k);       // rt[m-2-k]
            #pragma unroll
            for (int k = 0; k < 4; ++k) {
                int mm = m - k;
                float dt_m1 = frcp(1.0f - rtv[k] * rv[k]);  // dt[mm-1]
                float s_up = dt_m * (s_m + sv[k] * r_m);
                float G = Fu + s_up;
                __stcs(&fu[base + (unsigned)mm * CCH], G);

                float tdm1 = tv[k] * dt_m1;
                float au = G * av[k] * (1.0f + rtv[k] * tdm1);
                __stcs(&ab[base + (unsigned)(mm - 1) * CCH], abv[k] + au);
                Fu = G * tdm1;

                s_m = sv[k];
                r_m = rv[k];
                dt_m = dt_m1;
            }
        }
        for (; m >= 2; --m) {                   // tail m = 3, 2
            unsigned idxm1 = base + (unsigned)(m - 1) * CCH;
            float s_m1 = __ldcs(&s[idxm1]);
            float r_m1 = __ldcs(&r[idxm1]);
            float t_m1 = __ldcs(&t[idxm1]);
            float a_m1 = __ldcs(&a[idxm1]);
            float ab_old = ab[idxm1];

            float rt_m2 = SH_R(m - 2);
            float dt_m1 = frcp(1.0f - rt_m2 * r_m1);

            float s_up_m = dt_m * (s_m + s_m1 * r_m);
            float G = Fu + s_up_m;
            __stcs(&fu[base + (unsigned)m * CCH], G);

            float tdm1 = t_m1 * dt_m1;
            float au = G * a_m1 * (1.0f + rt_m2 * tdm1);
            __stcs(&ab[idxm1], ab_old + au);
            Fu = G * tdm1;

            s_m = s_m1;
            r_m = r_m1;
            dt_m = dt_m1;
        }

        // m = 1 and m = 0 epilogue; loop left s_m=s[1], r_m=r[1], dt_m=dt[1]
        float s0 = __ldcs(&s[base]);
        float t0 = __ldcs(&t[base]);
        float a0 = __ldcs(&a[base]);
        float s_up1 = dt_m * (s_m + s0 * r_m);
        float flux1 = Fu + s_up1;
        __stcs(&fu[base + CCH], flux1);           // flux_up[1]
        __stcs(&ab[base], flux1 * a0);            // absorbed[0] (down = 0)
        __stcs(&fu[base], flux1 * t0 + s0);       // flux_up[0]
    }

#undef SH_R
}

extern "C" void kernel_launch(void* const* d_in, const int* in_sizes, int n_in,
                              void* d_out, int out_size)
{
    const float* a = (const float*)d_in[0];
    const float* r = (const float*)d_in[1];
    const float* t = (const float*)d_in[2];
    const float* s = (const float*)d_in[3];
    float* out = (float*)d_out;

    cudaFuncSetAttribute(adding_doubling_kernel,
                         cudaFuncAttributeMaxDynamicSharedMemorySize,
                         (int)SMEM_BYTES);

    const int total = BCOL * CCH;                 // 262144 threads
    const int grid = (total + BLOCK - 1) / BLOCK; // 2048 blocks
    adding_doubling_kernel<<<grid, BLOCK, SMEM_BYTES>>>(a, r, t, s, out);
}

// round 6
// speedup vs baseline: 3.1167x; 1.1732x over previous
#include <cuda_runtime.h>

// Problem constants (from reference: B=2048, N=60, C=128)
#define BCOL 2048
#define NL   60
#define CCH  128
#define BLOCK 128

// dynamic smem: ONE per-thread array of NL floats, [layer][thread].
// Holds rs[] (phase A), progressively overwritten by rt[] (phase B).
#define SMEM_FLOATS (NL * BLOCK)
#define SMEM_BYTES  (SMEM_FLOATS * sizeof(float))

__device__ __forceinline__ float frcp(float x) {
    return __fdividef(1.0f, x);     // MUFU.RCP path, ~2ulp
}

struct BufA { float rv[4], tv[4]; };
struct BufB { float sv[4], rv[4], tv[4], av[4]; };
struct BufC { float sv[4], rv[4], tv[4], av[4], abv[4]; };

struct BState { float s_prev, r_prev, ds_prev, rt_run, F; };
struct CState { float Fu, s_m, r_m, dt_m; };

// ---- load helpers: issue all batch loads back-to-back (max MLP) ----
__device__ __forceinline__ void loadA(BufA& B, const float* __restrict__ r,
                                      const float* __restrict__ t,
                                      unsigned base, int l0) {
    #pragma unroll
    for (int k = 0; k < 4; ++k) {
        unsigned idx = base + (unsigned)(l0 - k) * CCH;
        B.rv[k] = r[idx];
        B.tv[k] = t[idx];
    }
}
__device__ __forceinline__ void loadB(BufB& B, const float* __restrict__ s,
                                      const float* __restrict__ r,
                                      const float* __restrict__ t,
                                      const float* __restrict__ a,
                                      unsigned base, int l0) {
    #pragma unroll
    for (int k = 0; k < 4; ++k) {
        unsigned idx = base + (unsigned)(l0 + k) * CCH;
        B.sv[k] = s[idx];
        B.rv[k] = r[idx];
        B.tv[k] = t[idx];
        B.av[k] = a[idx];
    }
}
__device__ __forceinline__ void loadC(BufC& B, const float* __restrict__ s,
                                      const float* __restrict__ r,
                                      const float* __restrict__ t,
                                      const float* __restrict__ a,
                                      const float* __restrict__ ab,
                                      unsigned base, int m0) {
    #pragma unroll
    for (int k = 0; k < 4; ++k) {
        unsigned idx = base + (unsigned)(m0 - 1 - k) * CCH;
        B.sv[k]  = __ldcs(&s[idx]);   // last use of inputs
        B.rv[k]  = __ldcs(&r[idx]);
        B.tv[k]  = __ldcs(&t[idx]);
        B.av[k]  = __ldcs(&a[idx]);
        B.abv[k] = ab[idx];           // absorbed_down (written in phase B)
    }
}

// ---- compute helpers (identical math to the passing R5 kernel) ----
__device__ __forceinline__ float compA(float rs_run, const BufA& B, int l0,
                                       float* sh, int tx) {
    #pragma unroll
    for (int k = 0; k < 4; ++k) {
        float dd = frcp(1.0f - rs_run * B.rv[k]);
        rs_run = B.rv[k] + rs_run * B.tv[k] * B.tv[k] * dd;
        sh[(l0 - k) * BLOCK + tx] = rs_run;
    }
    return rs_run;
}

__device__ __forceinline__ void compB(BState& st, const BufB& Bu, int l0,
                                      float* sh, int tx, unsigned base,
                                      float* fd, float* ab) {
    float rsv[4];
    #pragma unroll
    for (int k = 0; k < 4; ++k)
        rsv[k] = sh[(l0 + k + 1) * BLOCK + tx];   // rs[l+1]
    #pragma unroll
    for (int k = 0; k < 4; ++k) {
        unsigned idx = base + (unsigned)(l0 + k) * CCH;
        float s_down = st.ds_prev * (st.s_prev + Bu.sv[k] * st.r_prev);
        float G = st.F + s_down;
        __stcs(&fd[idx], G);

        float dsl = frcp(1.0f - rsv[k] * Bu.rv[k]);    // ds[l]
        float td = Bu.tv[k] * dsl;
        ab[idx] = Bu.av[k] * (1.0f + rsv[k] * td) * G; // re-read in C
        st.F = G * td;
        st.ds_prev = dsl;

        float dd = frcp(1.0f - st.rt_run * Bu.rv[k]);
        st.rt_run = Bu.rv[k] + st.rt_run * Bu.tv[k] * Bu.tv[k] * dd;
        sh[(l0 + k) * BLOCK + tx] = st.rt_run;         // overwrite dead rs

        st.s_prev = Bu.sv[k];
        st.r_prev = Bu.rv[k];
    }
}

__device__ __forceinline__ void compC(CState& st, const BufC& Bu, int m0,
                                      float* sh, int tx, unsigned base,
                                      float* fu, float* ab) {
    float rtv[4];
    #pragma unroll
    for (int k = 0; k < 4; ++k)
        rtv[k] = sh[(m0 - 2 - k) * BLOCK + tx];   // rt[m-2]
    #pragma unroll
    for (int k = 0; k < 4; ++k) {
        int mm = m0 - k;
        float dt_m1 = frcp(1.0f - rtv[k] * Bu.rv[k]);   // dt[mm-1]
        float s_up = st.dt_m * (st.s_m + Bu.sv[k] * st.r_m);
        float G = st.Fu + s_up;
        __stcs(&fu[base + (unsigned)mm * CCH], G);

        float tdm1 = Bu.tv[k] * dt_m1;
        float au = G * Bu.av[k] * (1.0f + rtv[k] * tdm1);
        __stcs(&ab[base + (unsigned)(mm - 1) * CCH], Bu.abv[k] + au);
        st.Fu = G * tdm1;

        st.s_m = Bu.sv[k];
        st.r_m = Bu.rv[k];
        st.dt_m = dt_m1;
    }
}

__global__ __launch_bounds__(BLOCK, 6)   // 85-reg cap, 6 blocks/SM
void adding_doubling_kernel(const float* __restrict__ a,
                            const float* __restrict__ r,
                            const float* __restrict__ t,
                            const float* __restrict__ s,
                            float* __restrict__ out)
{
    extern __shared__ float smem[];
    const int tx = threadIdx.x;

    const unsigned tid = blockIdx.x * BLOCK + tx;
    const unsigned base = (tid >> 7) * (NL * CCH) + (tid & (CCH - 1));
    const unsigned BNC  = BCOL * NL * CCH;

    float* fd = out;            // flux_down
    float* fu = out + BNC;      // flux_up
    float* ab = out + 2u * BNC; // absorbed

#define SH_R(l) smem[(l) * BLOCK + tx]

    // ---------------- Phase A: bottom-up cumulative surface reflection ----
    // 14 batches at l0 = 58,54,...,6 (covering l=58..3), tail l=2,1
    {
        float rs_run = r[base + (NL - 1) * CCH];
        SH_R(NL - 1) = rs_run;

        BufA A0, A1;
        int l = NL - 2;                       // 58
        loadA(A0, r, t, base, l);
        #pragma unroll 1
        for (int it = 0; it < 6; ++it, l -= 8) {
            loadA(A1, r, t, base, l - 4);
            rs_run = compA(rs_run, A0, l, smem, tx);
            loadA(A0, r, t, base, l - 8);
            rs_run = compA(rs_run, A1, l - 4, smem, tx);
        }
        // l == 10; A0 holds batch 10
        loadA(A1, r, t, base, 6);
        rs_run = compA(rs_run, A0, 10, smem, tx);
        rs_run = compA(rs_run, A1, 6, smem, tx);

        #pragma unroll
        for (int l2 = 2; l2 >= 1; --l2) {     // tail
            unsigned idx = base + (unsigned)l2 * CCH;
            float rl = r[idx], tl = t[idx];
            float dd = frcp(1.0f - rs_run * rl);
            rs_run = rl + rs_run * tl * tl * dd;
            SH_R(l2) = rs_run;
        }
    }

    // ---------------- Phase B: forward — down flux + top-down rt ----------
    // 14 batches at l0 = 1,5,...,53 (covering l=1..56), tail l=57..59
    {
        BState st;
        st.s_prev = s[base];
        st.r_prev = r[base];
        float rs1 = SH_R(1);
        st.ds_prev = frcp(1.0f - rs1 * st.r_prev);   // ds[0]
        st.rt_run = st.r_prev;                        // rt[0]
        SH_R(0) = st.rt_run;
        __stcs(&fd[base], 0.0f);
        st.F = 0.0f;

        BufB B0, B1;
        int l = 1;
        loadB(B0, s, r, t, a, base, 1);
        #pragma unroll 1
        for (int it = 0; it < 6; ++it, l += 8) {
            loadB(B1, s, r, t, a, base, l + 4);
            compB(st, B0, l, smem, tx, base, fd, ab);
            loadB(B0, s, r, t, a, base, l + 8);
            compB(st, B1, l + 4, smem, tx, base, fd, ab);
        }
        // l == 49; B0 holds batch 49
        loadB(B1, s, r, t, a, base, 53);
        compB(st, B0, 49, smem, tx, base, fd, ab);
        compB(st, B1, 53, smem, tx, base, fd, ab);

        #pragma unroll
        for (int l2 = 57; l2 < NL; ++l2) {    // tail l = 57, 58, 59
            unsigned idx = base + (unsigned)l2 * CCH;
            float sl = s[idx], rl = r[idx], tl = t[idx], al = a[idx];

            float s_down = st.ds_prev * (st.s_prev + sl * st.r_prev);
            float G = st.F + s_down;
            __stcs(&fd[idx], G);

            float absd;
            if (l2 < NL - 1) {
                float rsl1 = SH_R(l2 + 1);
                float dsl  = frcp(1.0f - rsl1 * rl);
                float td = tl * dsl;
                absd = al * (1.0f + rsl1 * td) * G;
                st.F = G * td;
                st.ds_prev = dsl;
            } else {
                absd = al * G;
            }
            ab[idx] = absd;

            float dd = frcp(1.0f - st.rt_run * rl);
            st.rt_run = rl + st.rt_run * tl * tl * dd;
            SH_R(l2) = st.rt_run;

            st.s_prev = sl;
            st.r_prev = rl;
        }
    }

    // ---------------- Phase C: reverse — up flux ---------------------------
    // 14 batches at m0 = 59,55,...,7 (covering m=59..4), tail m=3,2, epilogue
    {
        CState st;
        st.Fu = 0.0f;
        unsigned idxN = base + (NL - 1) * CCH;
        st.s_m = __ldcs(&s[idxN]);
        st.r_m = __ldcs(&r[idxN]);
        st.dt_m = frcp(1.0f - SH_R(NL - 2) * st.r_m);   // dt[N-1]

        BufC C0, C1;
        int m = NL - 1;                        // 59
        loadC(C0, s, r, t, a, ab, base, 59);
        #pragma unroll 1
        for (int it = 0; it < 6; ++it, m -= 8) {
            loadC(C1, s, r, t, a, ab, base, m - 4);
            compC(st, C0, m, smem, tx, base, fu, ab);
            loadC(C0, s, r, t, a, ab, base, m - 8);
            compC(st, C1, m - 4, smem, tx, base, fu, ab);
        }
        // m == 11; C0 holds batch 11
        loadC(C1, s, r, t, a, ab, base, 7);
        compC(st, C0, 11, smem, tx, base, fu, ab);
        compC(st, C1, 7, smem, tx, base, fu, ab);

        #pragma unroll
        for (int m2 = 3; m2 >= 2; --m2) {      // tail m = 3, 2
            unsigned idxm1 = base + (unsigned)(m2 - 1) * CCH;
            float s_m1 = __ldcs(&s[idxm1]);
            float r_m1 = __ldcs(&r[idxm1]);
            float t_m1 = __ldcs(&t[idxm1]);
            float a_m1 = __ldcs(&a[idxm1]);
            float ab_old = ab[idxm1];

            float rt_m2 = SH_R(m2 - 2);
            float dt_m1 = frcp(1.0f - rt_m2 * r_m1);

            float s_up_m = st.dt_m * (st.s_m + s_m1 * st.r_m);
            float G = st.Fu + s_up_m;
            __stcs(&fu[base + (unsigned)m2 * CCH], G);

            float tdm1 = t_m1 * dt_m1;
            float au = G * a_m1 * (1.0f + rt_m2 * tdm1);
            __stcs(&ab[idxm1], ab_old + au);
            st.Fu = G * tdm1;

            st.s_m = s_m1;
            st.r_m = r_m1;
            st.dt_m = dt_m1;
        }

        // m = 1 and m = 0 epilogue; state: s_m=s[1], r_m=r[1], dt_m=dt[1]
        float s0 = __ldcs(&s[base]);
        float t0 = __ldcs(&t[base]);
        float a0 = __ldcs(&a[base]);
        float s_up1 = st.dt_m * (st.s_m + s0 * st.r_m);
        float flux1 = st.Fu + s_up1;
        __stcs(&fu[base + CCH], flux1);           // flux_up[1]
        __stcs(&ab[base], flux1 * a0);            // absorbed[0] (down = 0)
        __stcs(&fu[base], flux1 * t0 + s0);       // flux_up[0]
    }

#undef SH_R
}

extern "C" void kernel_launch(void* const* d_in, const int* in_sizes, int n_in,
                              void* d_out, int out_size)
{
    const float* a = (const float*)d_in[0];
    const float* r = (const float*)d_in[1];
    const float* t = (const float*)d_in[2];
    const float* s = (const float*)d_in[3];
    float* out = (float*)d_out;

    cudaFuncSetAttribute(adding_doubling_kernel,
                         cudaFuncAttributeMaxDynamicSharedMemorySize,
                         (int)SMEM_BYTES);

    const int total = BCOL * CCH;                 // 262144 threads
    const int grid = (total + BLOCK - 1) / BLOCK; // 2048 blocks
    adding_doubling_kernel<<<grid, BLOCK, SMEM_BYTES>>>(a, r, t, s, out);
}

// round 7
// speedup vs baseline: 3.1676x; 1.0163x over previous
#include <cuda_runtime.h>

// Problem constants (from reference: B=2048, N=60, C=128)
#define BCOL 2048
#define NL   60
#define CCH  128
#define BLOCK 128

// dynamic smem: ONE per-thread array of NL floats, [layer][thread].
// Holds rs[] (phase A), progressively overwritten by rt[] (phase B).
// PADDED to 36 KB to cap residency at 5 blocks/SM: concurrent working set
// 740 blocks x ~150 KB ~= 111 MB < 126 MB L2, so phase-to-phase re-reads
// (A->B and B->C) become L2 hits instead of DRAM misses.
#define SMEM_FLOATS (NL * BLOCK)
#define SMEM_BYTES  (36 * 1024)

__device__ __forceinline__ float frcp(float x) {
    return __fdividef(1.0f, x);     // MUFU.RCP path, ~2ulp
}

struct BufA { float rv[4], tv[4]; };
struct BufB { float sv[4], rv[4], tv[4], av[4]; };
struct BufC { float sv[4], rv[4], tv[4], av[4], abv[4]; };

struct BState { float s_prev, r_prev, ds_prev, rt_run, F; };
struct CState { float Fu, s_m, r_m, dt_m; };

// ---- load helpers: issue all batch loads back-to-back (max MLP) ----
__device__ __forceinline__ void loadA(BufA& B, const float* __restrict__ r,
                                      const float* __restrict__ t,
                                      unsigned base, int l0) {
    #pragma unroll
    for (int k = 0; k < 4; ++k) {
        unsigned idx = base + (unsigned)(l0 - k) * CCH;
        B.rv[k] = r[idx];
        B.tv[k] = t[idx];
    }
}
__device__ __forceinline__ void loadB(BufB& B, const float* __restrict__ s,
                                      const float* __restrict__ r,
                                      const float* __restrict__ t,
                                      const float* __restrict__ a,
                                      unsigned base, int l0) {
    #pragma unroll
    for (int k = 0; k < 4; ++k) {
        unsigned idx = base + (unsigned)(l0 + k) * CCH;
        B.sv[k] = s[idx];
        B.rv[k] = r[idx];
        B.tv[k] = t[idx];
        B.av[k] = a[idx];
    }
}
__device__ __forceinline__ void loadC(BufC& B, const float* __restrict__ s,
                                      const float* __restrict__ r,
                                      const float* __restrict__ t,
                                      const float* __restrict__ a,
                                      const float* __restrict__ ab,
                                      unsigned base, int m0) {
    #pragma unroll
    for (int k = 0; k < 4; ++k) {
        unsigned idx = base + (unsigned)(m0 - 1 - k) * CCH;
        B.sv[k]  = __ldcs(&s[idx]);   // last use of inputs
        B.rv[k]  = __ldcs(&r[idx]);
        B.tv[k]  = __ldcs(&t[idx]);
        B.av[k]  = __ldcs(&a[idx]);
        B.abv[k] = __ldcs(&ab[idx]);  // read once, then overwritten
    }
}

// ---- compute helpers (identical math to the passing R6 kernel) ----
__device__ __forceinline__ float compA(float rs_run, const BufA& B, int l0,
                                       float* sh, int tx) {
    #pragma unroll
    for (int k = 0; k < 4; ++k) {
        float dd = frcp(1.0f - rs_run * B.rv[k]);
        rs_run = B.rv[k] + rs_run * B.tv[k] * B.tv[k] * dd;
        sh[(l0 - k) * BLOCK + tx] = rs_run;
    }
    return rs_run;
}

__device__ __forceinline__ void compB(BState& st, const BufB& Bu, int l0,
                                      float* sh, int tx, unsigned base,
                                      float* fd, float* ab) {
    float rsv[4];
    #pragma unroll
    for (int k = 0; k < 4; ++k)
        rsv[k] = sh[(l0 + k + 1) * BLOCK + tx];   // rs[l+1]
    #pragma unroll
    for (int k = 0; k < 4; ++k) {
        unsigned idx = base + (unsigned)(l0 + k) * CCH;
        float s_down = st.ds_prev * (st.s_prev + Bu.sv[k] * st.r_prev);
        float G = st.F + s_down;
        __stcs(&fd[idx], G);

        float dsl = frcp(1.0f - rsv[k] * Bu.rv[k]);    // ds[l]
        float td = Bu.tv[k] * dsl;
        ab[idx] = Bu.av[k] * (1.0f + rsv[k] * td) * G; // re-read in C
        st.F = G * td;
        st.ds_prev = dsl;

        float dd = frcp(1.0f - st.rt_run * Bu.rv[k]);
        st.rt_run = Bu.rv[k] + st.rt_run * Bu.tv[k] * Bu.tv[k] * dd;
        sh[(l0 + k) * BLOCK + tx] = st.rt_run;         // overwrite dead rs

        st.s_prev = Bu.sv[k];
        st.r_prev = Bu.rv[k];
    }
}

__device__ __forceinline__ void compC(CState& st, const BufC& Bu, int m0,
                                      float* sh, int tx, unsigned base,
                                      float* fu, float* ab) {
    float rtv[4];
    #pragma unroll
    for (int k = 0; k < 4; ++k)
        rtv[k] = sh[(m0 - 2 - k) * BLOCK + tx];   // rt[m-2]
    #pragma unroll
    for (int k = 0; k < 4; ++k) {
        int mm = m0 - k;
        float dt_m1 = frcp(1.0f - rtv[k] * Bu.rv[k]);   // dt[mm-1]
        float s_up = st.dt_m * (st.s_m + Bu.sv[k] * st.r_m);
        float G = st.Fu + s_up;
        __stcs(&fu[base + (unsigned)mm * CCH], G);

        float tdm1 = Bu.tv[k] * dt_m1;
        float au = G * Bu.av[k] * (1.0f + rtv[k] * tdm1);
        __stcs(&ab[base + (unsigned)(mm - 1) * CCH], Bu.abv[k] + au);
        st.Fu = G * tdm1;

        st.s_m = Bu.sv[k];
        st.r_m = Bu.rv[k];
        st.dt_m = dt_m1;
    }
}

__global__ __launch_bounds__(BLOCK, 5)   // 5 blocks/SM, reg cap 102
void adding_doubling_kernel(const float* __restrict__ a,
                            const float* __restrict__ r,
                            const float* __restrict__ t,
                            const float* __restrict__ s,
                            float* __restrict__ out)
{
    extern __shared__ float smem[];
    const int tx = threadIdx.x;

    const unsigned tid = blockIdx.x * BLOCK + tx;
    const unsigned base = (tid >> 7) * (NL * CCH) + (tid & (CCH - 1));
    const unsigned BNC  = BCOL * NL * CCH;

    float* fd = out;            // flux_down
    float* fu = out + BNC;      // flux_up
    float* ab = out + 2u * BNC; // absorbed

#define SH_R(l) smem[(l) * BLOCK + tx]

    // ---------------- Phase A: bottom-up cumulative surface reflection ----
    // 14 batches at l0 = 58,54,...,6 (covering l=58..3), tail l=2,1
    {
        float rs_run = r[base + (NL - 1) * CCH];
        SH_R(NL - 1) = rs_run;

        BufA A0, A1;
        int l = NL - 2;                       // 58
        loadA(A0, r, t, base, l);
        #pragma unroll 1
        for (int it = 0; it < 6; ++it, l -= 8) {
            loadA(A1, r, t, base, l - 4);
            rs_run = compA(rs_run, A0, l, smem, tx);
            loadA(A0, r, t, base, l - 8);
            rs_run = compA(rs_run, A1, l - 4, smem, tx);
        }
        // l == 10; A0 holds batch 10
        loadA(A1, r, t, base, 6);
        rs_run = compA(rs_run, A0, 10, smem, tx);
        rs_run = compA(rs_run, A1, 6, smem, tx);

        #pragma unroll
        for (int l2 = 2; l2 >= 1; --l2) {     // tail
            unsigned idx = base + (unsigned)l2 * CCH;
            float rl = r[idx], tl = t[idx];
            float dd = frcp(1.0f - rs_run * rl);
            rs_run = rl + rs_run * tl * tl * dd;
            SH_R(l2) = rs_run;
        }
    }

    // ---------------- Phase B: forward — down flux + top-down rt ----------
    // 14 batches at l0 = 1,5,...,53 (covering l=1..56), tail l=57..59
    {
        BState st;
        st.s_prev = s[base];
        st.r_prev = r[base];
        float rs1 = SH_R(1);
        st.ds_prev = frcp(1.0f - rs1 * st.r_prev);   // ds[0]
        st.rt_run = st.r_prev;                        // rt[0]
        SH_R(0) = st.rt_run;
        __stcs(&fd[base], 0.0f);
        st.F = 0.0f;

        BufB B0, B1;
        int l = 1;
        loadB(B0, s, r, t, a, base, 1);
        #pragma unroll 1
        for (int it = 0; it < 6; ++it, l += 8) {
            loadB(B1, s, r, t, a, base, l + 4);
            compB(st, B0, l, smem, tx, base, fd, ab);
            loadB(B0, s, r, t, a, base, l + 8);
            compB(st, B1, l + 4, smem, tx, base, fd, ab);
        }
        // l == 49; B0 holds batch 49
        loadB(B1, s, r, t, a, base, 53);
        compB(st, B0, 49, smem, tx, base, fd, ab);
        compB(st, B1, 53, smem, tx, base, fd, ab);

        #pragma unroll
        for (int l2 = 57; l2 < NL; ++l2) {    // tail l = 57, 58, 59
            unsigned idx = base + (unsigned)l2 * CCH;
            float sl = s[idx], rl = r[idx], tl = t[idx], al = a[idx];

            float s_down = st.ds_prev * (st.s_prev + sl * st.r_prev);
            float G = st.F + s_down;
            __stcs(&fd[idx], G);

            float absd;
            if (l2 < NL - 1) {
                float rsl1 = SH_R(l2 + 1);
                float dsl  = frcp(1.0f - rsl1 * rl);
                float td = tl * dsl;
                absd = al * (1.0f + rsl1 * td) * G;
                st.F = G * td;
                st.ds_prev = dsl;
            } else {
                absd = al * G;
            }
            ab[idx] = absd;

            float dd = frcp(1.0f - st.rt_run * rl);
            st.rt_run = rl + st.rt_run * tl * tl * dd;
            SH_R(l2) = st.rt_run;

            st.s_prev = sl;
            st.r_prev = rl;
        }
    }

    // ---------------- Phase C: reverse — up flux ---------------------------
    // 14 batches at m0 = 59,55,...,7 (covering m=59..4), tail m=3,2, epilogue
    {
        CState st;
        st.Fu = 0.0f;
        unsigned idxN = base + (NL - 1) * CCH;
        st.s_m = __ldcs(&s[idxN]);
        st.r_m = __ldcs(&r[idxN]);
        st.dt_m = frcp(1.0f - SH_R(NL - 2) * st.r_m);   // dt[N-1]

        BufC C0, C1;
        int m = NL - 1;                        // 59
        loadC(C0, s, r, t, a, ab, base, 59);
        #pragma unroll 1
        for (int it = 0; it < 6; ++it, m -= 8) {
            loadC(C1, s, r, t, a, ab, base, m - 4);
            compC(st, C0, m, smem, tx, base, fu, ab);
            loadC(C0, s, r, t, a, ab, base, m - 8);
            compC(st, C1, m - 4, smem, tx, base, fu, ab);
        }
        // m == 11; C0 holds batch 11
        loadC(C1, s, r, t, a, ab, base, 7);
        compC(st, C0, 11, smem, tx, base, fu, ab);
        compC(st, C1, 7, smem, tx, base, fu, ab);

        #pragma unroll
        for (int m2 = 3; m2 >= 2; --m2) {      // tail m = 3, 2
            unsigned idxm1 = base + (unsigned)(m2 - 1) * CCH;
            float s_m1 = __ldcs(&s[idxm1]);
            float r_m1 = __ldcs(&r[idxm1]);
            float t_m1 = __ldcs(&t[idxm1]);
            float a_m1 = __ldcs(&a[idxm1]);
            float ab_old = __ldcs(&ab[idxm1]);

            float rt_m2 = SH_R(m2 - 2);
            float dt_m1 = frcp(1.0f - rt_m2 * r_m1);

            float s_up_m = st.dt_m * (st.s_m + s_m1 * st.r_m);
            float G = st.Fu + s_up_m;
            __stcs(&fu[base + (unsigned)m2 * CCH], G);

            float tdm1 = t_m1 * dt_m1;
            float au = G * a_m1 * (1.0f + rt_m2 * tdm1);
            __stcs(&ab[idxm1], ab_old + au);
            st.Fu = G * tdm1;

            st.s_m = s_m1;
            st.r_m = r_m1;
            st.dt_m = dt_m1;
        }

        // m = 1 and m = 0 epilogue; state: s_m=s[1], r_m=r[1], dt_m=dt[1]
        float s0 = __ldcs(&s[base]);
        float t0 = __ldcs(&t[base]);
        float a0 = __ldcs(&a[base]);
        float s_up1 = st.dt_m * (st.s_m + s0 * st.r_m);
        float flux1 = st.Fu + s_up1;
        __stcs(&fu[base + CCH], flux1);           // flux_up[1]
        __stcs(&ab[base], flux1 * a0);            // absorbed[0] (down = 0)
        __stcs(&fu[base], flux1 * t0 + s0);       // flux_up[0]
    }

#undef SH_R
}

extern "C" void kernel_launch(void* const* d_in, const int* in_sizes, int n_in,
                              void* d_out, int out_size)
{
    const float* a = (const float*)d_in[0];
    const float* r = (const float*)d_in[1];
    const float* t = (const float*)d_in[2];
    const float* s = (const float*)d_in[3];
    float* out = (float*)d_out;

    cudaFuncSetAttribute(adding_doubling_kernel,
                         cudaFuncAttributeMaxDynamicSharedMemorySize,
                         (int)SMEM_BYTES);

    const int total = BCOL * CCH;                 // 262144 threads
    const int grid = (total + BLOCK - 1) / BLOCK; // 2048 blocks
    adding_doubling_kernel<<<grid, BLOCK, SMEM_BYTES>>>(a, r, t, s, out);
}